// round 11
// baseline (speedup 1.0000x reference)
#include <cuda_runtime.h>
#include <cuda_fp16.h>
#include <cstdint>

#define Z_STRIDE 528                      // 256 fp16 + 16B pad -> conflict-free ldmatrix
#define SMEM_TOTAL (256 * Z_STRIDE)       // 135168 B, 1 CTA/SM

__device__ uint32_t g_wfrag[32768];       // A fragments: [wb(8)][lane(32)][fi(128)]

__device__ __forceinline__ uint32_t s2u(const void* p){
    uint32_t a;
    asm("{ .reg .u64 t; cvta.to.shared.u64 t, %1; cvt.u32.u64 %0, t; }" : "=r"(a) : "l"(p));
    return a;
}

// ---------------- weight prep (A fragments for mma.sync) ----------------
__global__ void __launch_bounds__(256) prep_weights(const float* __restrict__ cw){
    const int idx = blockIdx.x * 256 + threadIdx.x;      // 32768
    int wb = idx >> 12;
    int ln = (idx >> 7) & 31;
    int fi = idx & 127;
    int kt = fi >> 3, mt = (fi >> 2) & 1, j = fi & 3;
    int o = wb * 32 + mt * 16 + (ln >> 2) + (j & 1) * 8;
    int c = kt * 16 + (ln & 3) * 2 + (j >> 1) * 8;
    float2 wv = *(const float2*)(cw + o * 256 + c);
    __half2 hw = __floats2half2_rn(wv.x, wv.y);
    g_wfrag[idx] = *(uint32_t*)&hw;
}

// ---------------- fused kernel: one 512-thread CTA per (b, h) ----------------
// 16 warps = 8 m-blocks (32 o-rows) x 2 w-halves (128 w) -> 4:1 HMMA:ldmatrix reuse
__global__ void __launch_bounds__(512, 1)
fused_ln_conv_relu(const float* __restrict__ x, const float* __restrict__ y,
                   const float* __restrict__ lnw, const float* __restrict__ lnb,
                   float* __restrict__ out)
{
    extern __shared__ __align__(128) char smem[];
    const uint32_t su = s2u(smem);
    const int tid = threadIdx.x, wid = tid >> 5, lane = tid & 31;
    const int b = blockIdx.x >> 8, h = blockIdx.x & 255;
    const size_t base_bh = ((size_t)b << 24) + ((size_t)h << 8);

    const float4 lwa = *(const float4*)(lnw + 4 * lane);
    const float4 lwb = *(const float4*)(lnw + 128 + 4 * lane);
    const float4 lba = *(const float4*)(lnb + 4 * lane);
    const float4 lbb = *(const float4*)(lnb + 128 + 4 * lane);

    // ---- phase 1: residual add + LayerNorm -> Z fp16 [256c][256w], 16 rows/warp ----
    {
        #pragma unroll 4
        for (int r = 0; r < 16; r++) {
            const int c = wid * 16 + r;
            const float* px = x + base_bh + ((size_t)c << 16) + 4 * lane;
            const float* py = y + base_bh + ((size_t)c << 16) + 4 * lane;
            float4 xa = *(const float4*)px;
            float4 xb = *(const float4*)(px + 128);
            float4 ya = *(const float4*)py;
            float4 yb = *(const float4*)(py + 128);
            float v0 = xa.x + ya.x, v1 = xa.y + ya.y, v2 = xa.z + ya.z, v3 = xa.w + ya.w;
            float v4 = xb.x + yb.x, v5 = xb.y + yb.y, v6 = xb.z + yb.z, v7 = xb.w + yb.w;
            float s = v0+v1+v2+v3+v4+v5+v6+v7;
            float q = v0*v0+v1*v1+v2*v2+v3*v3+v4*v4+v5*v5+v6*v6+v7*v7;
            #pragma unroll
            for (int o_ = 16; o_; o_ >>= 1) {
                s += __shfl_xor_sync(0xFFFFFFFFu, s, o_);
                q += __shfl_xor_sync(0xFFFFFFFFu, q, o_);
            }
            const float mean = s * (1.0f / 256.0f);
            const float rstd = rsqrtf(q * (1.0f / 256.0f) - mean * mean + 1e-5f);
            __half2 h01 = __floats2half2_rn((v0-mean)*rstd*lwa.x + lba.x, (v1-mean)*rstd*lwa.y + lba.y);
            __half2 h23 = __floats2half2_rn((v2-mean)*rstd*lwa.z + lba.z, (v3-mean)*rstd*lwa.w + lba.w);
            __half2 h45 = __floats2half2_rn((v4-mean)*rstd*lwb.x + lbb.x, (v5-mean)*rstd*lwb.y + lbb.y);
            __half2 h67 = __floats2half2_rn((v6-mean)*rstd*lwb.z + lbb.z, (v7-mean)*rstd*lwb.w + lbb.w);
            char* zr = smem + c * Z_STRIDE;
            *(uint2*)(zr + 8 * lane)       = make_uint2(*(uint32_t*)&h01, *(uint32_t*)&h23);
            *(uint2*)(zr + 256 + 8 * lane) = make_uint2(*(uint32_t*)&h45, *(uint32_t*)&h67);
        }
    }
    __syncthreads();

    // ---- phase 2: GEMM D[o,w] = sum_c W[o,c] * Z[c,w] ----
    const int mb = wid >> 1;              // m-block: 32 o-rows
    const int wh = wid & 1;               // w-half: 128 w
    const uint4* wf = (const uint4*)g_wfrag + ((mb * 32 + lane) * 32);
    const int g = lane >> 2, t = lane & 3;
    const uint32_t krow_off = ((uint32_t)((lane >> 3) & 1)) * 8 + (lane & 7);
    const uint32_t ncol_off = ((uint32_t)(lane >> 4)) * 8;
    float* outp = out + ((size_t)b << 24) + ((size_t)(mb * 32 + g) << 16) + ((size_t)h << 8)
                      + wh * 128;

    #pragma unroll 1
    for (int wc = 0; wc < 4; wc++) {                 // w-chunks of 32 within the 128-half
        float acc[2][4][4] = {};
        #pragma unroll 2
        for (int kt = 0; kt < 16; kt++) {
            uint4 a0 = __ldg(wf + kt * 2);
            uint4 a1 = __ldg(wf + kt * 2 + 1);
            uint32_t bf[4][2];
            #pragma unroll
            for (int qq = 0; qq < 2; qq++) {
                uint32_t addr = su + (kt * 16 + krow_off) * Z_STRIDE
                                   + (uint32_t)(wh * 128 + wc * 32 + qq * 16) * 2 + ncol_off * 2;
                asm volatile("ldmatrix.sync.aligned.m8n8.x4.trans.shared.b16 {%0,%1,%2,%3}, [%4];"
                             : "=r"(bf[2*qq][0]), "=r"(bf[2*qq][1]),
                               "=r"(bf[2*qq+1][0]), "=r"(bf[2*qq+1][1])
                             : "r"(addr));
            }
            #pragma unroll
            for (int nt = 0; nt < 4; nt++) {
                asm volatile(
                    "mma.sync.aligned.m16n8k16.row.col.f32.f16.f16.f32 "
                    "{%0,%1,%2,%3}, {%4,%5,%6,%7}, {%8,%9}, {%0,%1,%2,%3};"
                    : "+f"(acc[0][nt][0]), "+f"(acc[0][nt][1]), "+f"(acc[0][nt][2]), "+f"(acc[0][nt][3])
                    : "r"(a0.x), "r"(a0.y), "r"(a0.z), "r"(a0.w),
                      "r"(bf[nt][0]), "r"(bf[nt][1]));
                asm volatile(
                    "mma.sync.aligned.m16n8k16.row.col.f32.f16.f16.f32 "
                    "{%0,%1,%2,%3}, {%4,%5,%6,%7}, {%8,%9}, {%0,%1,%2,%3};"
                    : "+f"(acc[1][nt][0]), "+f"(acc[1][nt][1]), "+f"(acc[1][nt][2]), "+f"(acc[1][nt][3])
                    : "r"(a1.x), "r"(a1.y), "r"(a1.z), "r"(a1.w),
                      "r"(bf[nt][0]), "r"(bf[nt][1]));
            }
        }
        // store this w-chunk with ReLU, direct from fragments (streaming)
        #pragma unroll
        for (int mt = 0; mt < 2; mt++) {
            #pragma unroll
            for (int nt = 0; nt < 4; nt++) {
                const int w = wc * 32 + nt * 8 + t * 2;
                float* p0 = outp + ((size_t)(mt * 16) << 16) + w;
                float2 v0 = make_float2(fmaxf(acc[mt][nt][0], 0.f), fmaxf(acc[mt][nt][1], 0.f));
                float2 v1 = make_float2(fmaxf(acc[mt][nt][2], 0.f), fmaxf(acc[mt][nt][3], 0.f));
                __stcs((float2*)p0, v0);
                __stcs((float2*)(p0 + (8 << 16)), v1);   // +8 o-rows
            }
        }
    }
}

extern "C" void kernel_launch(void* const* d_in, const int* in_sizes, int n_in,
                              void* d_out, int out_size) {
    (void)in_sizes; (void)n_in; (void)out_size;
    const float* x   = (const float*)d_in[0];
    const float* y   = (const float*)d_in[1];
    const float* lnw = (const float*)d_in[2];
    const float* lnb = (const float*)d_in[3];
    const float* cw  = (const float*)d_in[4];
    float* out = (float*)d_out;

    cudaFuncSetAttribute(fused_ln_conv_relu, cudaFuncAttributeMaxDynamicSharedMemorySize, SMEM_TOTAL);

    prep_weights<<<128, 256>>>(cw);
    fused_ln_conv_relu<<<1024, 512, SMEM_TOTAL>>>(x, y, lnw, lnb, out);
}

// round 13
// speedup vs baseline: 1.2249x; 1.2249x over previous
#include <cuda_runtime.h>
#include <cuda_fp16.h>
#include <cstdint>

#define Z_STRIDE 528                       // 256 fp16 + 16B pad -> conflict-free ldmatrix
#define Z_BYTES  (256 * Z_STRIDE)          // 135168
#define OFF_RAW  Z_BYTES                   // 2 stages x 32 KB raw (x:16KB, y:16KB)
#define RAW_STAGE 32768
#define SMEM_TOTAL (Z_BYTES + 2 * RAW_STAGE)   // 200704 B

__device__ uint32_t g_wfrag[32768];        // A fragments: [wb(8)][lane(32)][fi(128)]

__device__ __forceinline__ uint32_t s2u(const void* p){
    uint32_t a;
    asm("{ .reg .u64 t; cvta.to.shared.u64 t, %1; cvt.u32.u64 %0, t; }" : "=r"(a) : "l"(p));
    return a;
}
__device__ __forceinline__ void cpasync16(uint32_t dst, const void* src){
    asm volatile("cp.async.cg.shared.global [%0], [%1], 16;" :: "r"(dst), "l"(src));
}

// ---------------- weight prep (A fragments for mma.sync) ----------------
__global__ void __launch_bounds__(256) prep_weights(const float* __restrict__ cw){
    const int idx = blockIdx.x * 256 + threadIdx.x;      // 32768
    int wb = idx >> 12;
    int ln = (idx >> 7) & 31;
    int fi = idx & 127;
    int kt = fi >> 3, mt = (fi >> 2) & 1, j = fi & 3;
    int o = wb * 32 + mt * 16 + (ln >> 2) + (j & 1) * 8;
    int c = kt * 16 + (ln & 3) * 2 + (j >> 1) * 8;
    float2 wv = *(const float2*)(cw + o * 256 + c);
    __half2 hw = __floats2half2_rn(wv.x, wv.y);
    g_wfrag[idx] = *(uint32_t*)&hw;
}

// ---------------- fused kernel: one 512-thread CTA per (b, h) ----------------
__global__ void __launch_bounds__(512, 1)
fused_ln_conv_relu(const float* __restrict__ x, const float* __restrict__ y,
                   const float* __restrict__ lnw, const float* __restrict__ lnb,
                   float* __restrict__ out)
{
    extern __shared__ __align__(128) char smem[];
    const uint32_t su = s2u(smem);
    const int tid = threadIdx.x, wid = tid >> 5, lane = tid & 31;
    const int b = blockIdx.x >> 8, h = blockIdx.x & 255;
    const size_t base_bh = ((size_t)b << 24) + ((size_t)h << 8);

    const float4 lwa = *(const float4*)(lnw + 4 * lane);
    const float4 lwb = *(const float4*)(lnw + 128 + 4 * lane);
    const float4 lba = *(const float4*)(lnb + 4 * lane);
    const float4 lbb = *(const float4*)(lnb + 128 + 4 * lane);

    // GEMM constants
    const int mb = wid >> 1;                 // 8 m-blocks of 32 o-rows
    const int whalf = wid & 1;               // 2 w-slots of 64 within each pass
    const uint4* wf = (const uint4*)g_wfrag + ((mb * 32 + lane) * 32);
    const int g = lane >> 2, t = lane & 3;
    const uint32_t krow_off = ((uint32_t)((lane >> 3) & 1)) * 8 + (lane & 7);
    const uint32_t ncol_off = ((uint32_t)(lane >> 4)) * 8;

    // prefetch helper: issues one 16-row chunk (x + y) into a raw stage
    #define PREFETCH(c_, st_) do {                                                  \
        int idx0 = tid, idx1 = tid + 512;                                           \
        int r0 = idx0 >> 6, c0_ = idx0 & 63;                                        \
        int r1 = idx1 >> 6, c1_ = idx1 & 63;                                        \
        size_t g0 = base_bh + ((size_t)((c_) * 16 + r0) << 16) + c0_ * 4;           \
        size_t g1 = base_bh + ((size_t)((c_) * 16 + r1) << 16) + c1_ * 4;           \
        uint32_t d0 = su + OFF_RAW + (st_) * RAW_STAGE + r0 * 1024 + c0_ * 16;      \
        uint32_t d1 = su + OFF_RAW + (st_) * RAW_STAGE + r1 * 1024 + c1_ * 16;      \
        cpasync16(d0, x + g0);                                                      \
        cpasync16(d0 + 16384, y + g0);                                              \
        cpasync16(d1, x + g1);                                                      \
        cpasync16(d1 + 16384, y + g1);                                              \
        asm volatile("cp.async.commit_group;" ::: "memory");                        \
    } while (0)

    PREFETCH(0, 0);
    PREFETCH(1, 1);

    float acc[2][8][4] = {};

    #pragma unroll 1
    for (int c = 0; c < 16; c++) {
        const int stage = c & 1;
        if (c < 15) { asm volatile("cp.async.wait_group 1;" ::: "memory"); }
        else        { asm volatile("cp.async.wait_group 0;" ::: "memory"); }
        __syncthreads();

        // ---- LN of one row (row wid of chunk c) from the raw stage ----
        {
            const float4* prx = (const float4*)(smem + OFF_RAW + stage * RAW_STAGE + wid * 1024);
            const float4* pry = (const float4*)(smem + OFF_RAW + stage * RAW_STAGE + 16384 + wid * 1024);
            float4 xa = prx[lane],      xb = prx[lane + 32];
            float4 ya = pry[lane],      yb = pry[lane + 32];
            float v0 = xa.x + ya.x, v1 = xa.y + ya.y, v2 = xa.z + ya.z, v3 = xa.w + ya.w;
            float v4 = xb.x + yb.x, v5 = xb.y + yb.y, v6 = xb.z + yb.z, v7 = xb.w + yb.w;
            float s = v0+v1+v2+v3+v4+v5+v6+v7;
            float q = v0*v0+v1*v1+v2*v2+v3*v3+v4*v4+v5*v5+v6*v6+v7*v7;
            #pragma unroll
            for (int o_ = 16; o_; o_ >>= 1) {
                s += __shfl_xor_sync(0xFFFFFFFFu, s, o_);
                q += __shfl_xor_sync(0xFFFFFFFFu, q, o_);
            }
            const float mean = s * (1.0f / 256.0f);
            const float rstd = rsqrtf(q * (1.0f / 256.0f) - mean * mean + 1e-5f);
            __half2 h01 = __floats2half2_rn((v0-mean)*rstd*lwa.x + lba.x, (v1-mean)*rstd*lwa.y + lba.y);
            __half2 h23 = __floats2half2_rn((v2-mean)*rstd*lwa.z + lba.z, (v3-mean)*rstd*lwa.w + lba.w);
            __half2 h45 = __floats2half2_rn((v4-mean)*rstd*lwb.x + lbb.x, (v5-mean)*rstd*lwb.y + lbb.y);
            __half2 h67 = __floats2half2_rn((v6-mean)*rstd*lwb.z + lbb.z, (v7-mean)*rstd*lwb.w + lbb.w);
            char* zr = smem + (c * 16 + wid) * Z_STRIDE;
            *(uint2*)(zr + 8 * lane)       = make_uint2(*(uint32_t*)&h01, *(uint32_t*)&h23);
            *(uint2*)(zr + 256 + 8 * lane) = make_uint2(*(uint32_t*)&h45, *(uint32_t*)&h67);
        }
        __syncthreads();

        // ---- launch next prefetch (stage just freed by LN) ----
        if (c < 14) PREFETCH(c + 2, stage);

        // ---- GEMM K-step kt = c, pass-1 tile: w in [whalf*64, whalf*64+64) ----
        {
            const int kt = c;
            uint4 a0 = __ldg(wf + kt * 2);
            uint4 a1 = __ldg(wf + kt * 2 + 1);
            uint32_t bf[8][2];
            #pragma unroll
            for (int qq = 0; qq < 4; qq++) {
                uint32_t addr = su + (kt * 16 + krow_off) * Z_STRIDE
                                   + (uint32_t)(whalf * 64 + qq * 16) * 2 + ncol_off * 2;
                asm volatile("ldmatrix.sync.aligned.m8n8.x4.trans.shared.b16 {%0,%1,%2,%3}, [%4];"
                             : "=r"(bf[2*qq][0]), "=r"(bf[2*qq][1]),
                               "=r"(bf[2*qq+1][0]), "=r"(bf[2*qq+1][1])
                             : "r"(addr));
            }
            #pragma unroll
            for (int nt = 0; nt < 8; nt++) {
                asm volatile(
                    "mma.sync.aligned.m16n8k16.row.col.f32.f16.f16.f32 "
                    "{%0,%1,%2,%3}, {%4,%5,%6,%7}, {%8,%9}, {%0,%1,%2,%3};"
                    : "+f"(acc[0][nt][0]), "+f"(acc[0][nt][1]), "+f"(acc[0][nt][2]), "+f"(acc[0][nt][3])
                    : "r"(a0.x), "r"(a0.y), "r"(a0.z), "r"(a0.w),
                      "r"(bf[nt][0]), "r"(bf[nt][1]));
                asm volatile(
                    "mma.sync.aligned.m16n8k16.row.col.f32.f16.f16.f32 "
                    "{%0,%1,%2,%3}, {%4,%5,%6,%7}, {%8,%9}, {%0,%1,%2,%3};"
                    : "+f"(acc[1][nt][0]), "+f"(acc[1][nt][1]), "+f"(acc[1][nt][2]), "+f"(acc[1][nt][3])
                    : "r"(a1.x), "r"(a1.y), "r"(a1.z), "r"(a1.w),
                      "r"(bf[nt][0]), "r"(bf[nt][1]));
            }
        }
    }

    // ---- store pass-1 tile (w in [whalf*64, +64)) with ReLU ----
    {
        float* outp = out + ((size_t)b << 24) + ((size_t)(mb * 32 + g) << 16) + ((size_t)h << 8);
        #pragma unroll
        for (int mt = 0; mt < 2; mt++) {
            #pragma unroll
            for (int nt = 0; nt < 8; nt++) {
                const int w = whalf * 64 + nt * 8 + t * 2;
                float* p0 = outp + ((size_t)(mt * 16) << 16) + w;
                float2 v0 = make_float2(fmaxf(acc[mt][nt][0], 0.f), fmaxf(acc[mt][nt][1], 0.f));
                float2 v1 = make_float2(fmaxf(acc[mt][nt][2], 0.f), fmaxf(acc[mt][nt][3], 0.f));
                __stcs((float2*)p0, v0);
                __stcs((float2*)(p0 + (8 << 16)), v1);
            }
        }
    }

    // ---- pass 2: w in [128 + whalf*64, +64), full K from retained Z ----
    {
        float acc2[2][8][4] = {};
        #pragma unroll 2
        for (int kt = 0; kt < 16; kt++) {
            uint4 a0 = __ldg(wf + kt * 2);
            uint4 a1 = __ldg(wf + kt * 2 + 1);
            uint32_t bf[8][2];
            #pragma unroll
            for (int qq = 0; qq < 4; qq++) {
                uint32_t addr = su + (kt * 16 + krow_off) * Z_STRIDE
                                   + (uint32_t)(128 + whalf * 64 + qq * 16) * 2 + ncol_off * 2;
                asm volatile("ldmatrix.sync.aligned.m8n8.x4.trans.shared.b16 {%0,%1,%2,%3}, [%4];"
                             : "=r"(bf[2*qq][0]), "=r"(bf[2*qq][1]),
                               "=r"(bf[2*qq+1][0]), "=r"(bf[2*qq+1][1])
                             : "r"(addr));
            }
            #pragma unroll
            for (int nt = 0; nt < 8; nt++) {
                asm volatile(
                    "mma.sync.aligned.m16n8k16.row.col.f32.f16.f16.f32 "
                    "{%0,%1,%2,%3}, {%4,%5,%6,%7}, {%8,%9}, {%0,%1,%2,%3};"
                    : "+f"(acc2[0][nt][0]), "+f"(acc2[0][nt][1]), "+f"(acc2[0][nt][2]), "+f"(acc2[0][nt][3])
                    : "r"(a0.x), "r"(a0.y), "r"(a0.z), "r"(a0.w),
                      "r"(bf[nt][0]), "r"(bf[nt][1]));
                asm volatile(
                    "mma.sync.aligned.m16n8k16.row.col.f32.f16.f16.f32 "
                    "{%0,%1,%2,%3}, {%4,%5,%6,%7}, {%8,%9}, {%0,%1,%2,%3};"
                    : "+f"(acc2[1][nt][0]), "+f"(acc2[1][nt][1]), "+f"(acc2[1][nt][2]), "+f"(acc2[1][nt][3])
                    : "r"(a1.x), "r"(a1.y), "r"(a1.z), "r"(a1.w),
                      "r"(bf[nt][0]), "r"(bf[nt][1]));
            }
        }
        float* outp = out + ((size_t)b << 24) + ((size_t)(mb * 32 + g) << 16) + ((size_t)h << 8);
        #pragma unroll
        for (int mt = 0; mt < 2; mt++) {
            #pragma unroll
            for (int nt = 0; nt < 8; nt++) {
                const int w = 128 + whalf * 64 + nt * 8 + t * 2;
                float* p0 = outp + ((size_t)(mt * 16) << 16) + w;
                float2 v0 = make_float2(fmaxf(acc2[mt][nt][0], 0.f), fmaxf(acc2[mt][nt][1], 0.f));
                float2 v1 = make_float2(fmaxf(acc2[mt][nt][2], 0.f), fmaxf(acc2[mt][nt][3], 0.f));
                __stcs((float2*)p0, v0);
                __stcs((float2*)(p0 + (8 << 16)), v1);
            }
        }
    }
    #undef PREFETCH
}

extern "C" void kernel_launch(void* const* d_in, const int* in_sizes, int n_in,
                              void* d_out, int out_size) {
    (void)in_sizes; (void)n_in; (void)out_size;
    const float* x   = (const float*)d_in[0];
    const float* y   = (const float*)d_in[1];
    const float* lnw = (const float*)d_in[2];
    const float* lnb = (const float*)d_in[3];
    const float* cw  = (const float*)d_in[4];
    float* out = (float*)d_out;

    cudaFuncSetAttribute(fused_ln_conv_relu, cudaFuncAttributeMaxDynamicSharedMemorySize, SMEM_TOTAL);

    prep_weights<<<128, 256>>>(cw);
    fused_ln_conv_relu<<<1024, 512, SMEM_TOTAL>>>(x, y, lnw, lnb, out);
}

// round 14
// speedup vs baseline: 1.4121x; 1.1528x over previous
#include <cuda_runtime.h>
#include <cuda_fp16.h>
#include <cstdint>

#define Z_STRIDE 528                      // 256 fp16 + 16B pad -> conflict-free ldmatrix
#define SMEM_TOTAL (256 * Z_STRIDE)       // 135168 B, 1 CTA/SM

__device__ uint32_t g_wfrag[32768];       // A fragments: [wb(8)][lane(32)][fi(128)]

__device__ __forceinline__ uint32_t s2u(const void* p){
    uint32_t a;
    asm("{ .reg .u64 t; cvta.to.shared.u64 t, %1; cvt.u32.u64 %0, t; }" : "=r"(a) : "l"(p));
    return a;
}

// ---------------- weight prep (A fragments for mma.sync) ----------------
__global__ void __launch_bounds__(256) prep_weights(const float* __restrict__ cw){
    const int idx = blockIdx.x * 256 + threadIdx.x;      // 32768
    int wb = idx >> 12;
    int ln = (idx >> 7) & 31;
    int fi = idx & 127;
    int kt = fi >> 3, mt = (fi >> 2) & 1, j = fi & 3;
    int o = wb * 32 + mt * 16 + (ln >> 2) + (j & 1) * 8;
    int c = kt * 16 + (ln & 3) * 2 + (j >> 1) * 8;
    float2 wv = *(const float2*)(cw + o * 256 + c);
    __half2 hw = __floats2half2_rn(wv.x, wv.y);
    g_wfrag[idx] = *(uint32_t*)&hw;
}

// ---------------- fused kernel: one 256-thread CTA per (b, h) ----------------
__global__ void __launch_bounds__(256, 1)
fused_ln_conv_relu(const float* __restrict__ x, const float* __restrict__ y,
                   const float* __restrict__ lnw, const float* __restrict__ lnb,
                   float* __restrict__ out)
{
    extern __shared__ __align__(128) char smem[];
    const uint32_t su = s2u(smem);
    const int tid = threadIdx.x, wid = tid >> 5, lane = tid & 31;
    const int b = blockIdx.x >> 8, h = blockIdx.x & 255;
    const size_t base_bh = ((size_t)b << 24) + ((size_t)h << 8);

    const float4 lwa = *(const float4*)(lnw + 4 * lane);
    const float4 lwb = *(const float4*)(lnw + 128 + 4 * lane);
    const float4 lba = *(const float4*)(lnb + 4 * lane);
    const float4 lbb = *(const float4*)(lnb + 128 + 4 * lane);

    // ---- phase 1: residual add + LayerNorm -> Z fp16 [256c][256w] ----
    // 32 rows/warp in 8 groups of 4; next group's 16 LDG.128 in flight during processing
    {
        float4 bufA[16], bufB[16];
        #define LN_LOAD(buf, grp) do {                                                  \
            _Pragma("unroll")                                                           \
            for (int j = 0; j < 4; j++) {                                               \
                const size_t ro = base_bh + ((size_t)(wid * 32 + (grp) * 4 + j) << 16)  \
                                  + 4 * lane;                                           \
                (buf)[j*4+0] = *(const float4*)(x + ro);                                \
                (buf)[j*4+1] = *(const float4*)(x + ro + 128);                          \
                (buf)[j*4+2] = *(const float4*)(y + ro);                                \
                (buf)[j*4+3] = *(const float4*)(y + ro + 128);                          \
            }                                                                           \
        } while (0)

        LN_LOAD(bufA, 0);
        #pragma unroll
        for (int grp = 0; grp < 8; grp++) {
            const float4* cur = (grp & 1) ? bufB : bufA;
            float4*       nxt = (grp & 1) ? bufA : bufB;
            if (grp < 7) LN_LOAD(nxt, grp + 1);
            #pragma unroll
            for (int j = 0; j < 4; j++) {
                const int c = wid * 32 + grp * 4 + j;
                float4 xa = cur[j*4+0], xb = cur[j*4+1];
                float4 ya = cur[j*4+2], yb = cur[j*4+3];
                float v0 = xa.x + ya.x, v1 = xa.y + ya.y, v2 = xa.z + ya.z, v3 = xa.w + ya.w;
                float v4 = xb.x + yb.x, v5 = xb.y + yb.y, v6 = xb.z + yb.z, v7 = xb.w + yb.w;
                float s = v0+v1+v2+v3+v4+v5+v6+v7;
                float q = v0*v0+v1*v1+v2*v2+v3*v3+v4*v4+v5*v5+v6*v6+v7*v7;
                #pragma unroll
                for (int o_ = 16; o_; o_ >>= 1) {
                    s += __shfl_xor_sync(0xFFFFFFFFu, s, o_);
                    q += __shfl_xor_sync(0xFFFFFFFFu, q, o_);
                }
                const float mean = s * (1.0f / 256.0f);
                const float rstd = rsqrtf(q * (1.0f / 256.0f) - mean * mean + 1e-5f);
                __half2 h01 = __floats2half2_rn((v0-mean)*rstd*lwa.x + lba.x, (v1-mean)*rstd*lwa.y + lba.y);
                __half2 h23 = __floats2half2_rn((v2-mean)*rstd*lwa.z + lba.z, (v3-mean)*rstd*lwa.w + lba.w);
                __half2 h45 = __floats2half2_rn((v4-mean)*rstd*lwb.x + lbb.x, (v5-mean)*rstd*lwb.y + lbb.y);
                __half2 h67 = __floats2half2_rn((v6-mean)*rstd*lwb.z + lbb.z, (v7-mean)*rstd*lwb.w + lbb.w);
                char* zr = smem + c * Z_STRIDE;
                *(uint2*)(zr + 8 * lane)       = make_uint2(*(uint32_t*)&h01, *(uint32_t*)&h23);
                *(uint2*)(zr + 256 + 8 * lane) = make_uint2(*(uint32_t*)&h45, *(uint32_t*)&h67);
            }
        }
        #undef LN_LOAD
    }
    __syncthreads();

    // ---- phase 2: GEMM D[o,w] = sum_c W[o,c] * Z[c,w]; warp owns 32 o-rows ----
    // kt-loop software-pipelined: B fragments (4 ldmatrix) + A fragments (2 LDG)
    // for step kt+1 issued before the 32 HMMAs of step kt.
    const uint4* wf = (const uint4*)g_wfrag + ((wid * 32 + lane) * 32);
    const int g = lane >> 2, t = lane & 3;
    const uint32_t krow_off = ((uint32_t)((lane >> 3) & 1)) * 8 + (lane & 7);
    const uint32_t ncol_off = ((uint32_t)(lane >> 4)) * 8;
    float* outp = out + ((size_t)b << 24) + ((size_t)(wid * 32 + g) << 16) + ((size_t)h << 8);

    #define LOADB(bf, kt, wc) do {                                                      \
        _Pragma("unroll")                                                               \
        for (int qq = 0; qq < 4; qq++) {                                                \
            uint32_t addr = su + ((kt) * 16 + krow_off) * Z_STRIDE                      \
                               + (uint32_t)((wc) * 64 + qq * 16) * 2 + ncol_off * 2;    \
            asm volatile("ldmatrix.sync.aligned.m8n8.x4.trans.shared.b16 "              \
                         "{%0,%1,%2,%3}, [%4];"                                         \
                         : "=r"((bf)[2*qq][0]), "=r"((bf)[2*qq][1]),                    \
                           "=r"((bf)[2*qq+1][0]), "=r"((bf)[2*qq+1][1])                 \
                         : "r"(addr));                                                  \
        }                                                                               \
    } while (0)

    #define MMAS(bf, a0, a1) do {                                                       \
        _Pragma("unroll")                                                               \
        for (int nt = 0; nt < 8; nt++) {                                                \
            asm volatile(                                                               \
                "mma.sync.aligned.m16n8k16.row.col.f32.f16.f16.f32 "                    \
                "{%0,%1,%2,%3}, {%4,%5,%6,%7}, {%8,%9}, {%0,%1,%2,%3};"                 \
                : "+f"(acc[0][nt][0]), "+f"(acc[0][nt][1]),                             \
                  "+f"(acc[0][nt][2]), "+f"(acc[0][nt][3])                              \
                : "r"((a0).x), "r"((a0).y), "r"((a0).z), "r"((a0).w),                   \
                  "r"((bf)[nt][0]), "r"((bf)[nt][1]));                                  \
            asm volatile(                                                               \
                "mma.sync.aligned.m16n8k16.row.col.f32.f16.f16.f32 "                    \
                "{%0,%1,%2,%3}, {%4,%5,%6,%7}, {%8,%9}, {%0,%1,%2,%3};"                 \
                : "+f"(acc[1][nt][0]), "+f"(acc[1][nt][1]),                             \
                  "+f"(acc[1][nt][2]), "+f"(acc[1][nt][3])                              \
                : "r"((a1).x), "r"((a1).y), "r"((a1).z), "r"((a1).w),                   \
                  "r"((bf)[nt][0]), "r"((bf)[nt][1]));                                  \
        }                                                                               \
    } while (0)

    #pragma unroll 1
    for (int wc = 0; wc < 4; wc++) {
        float acc[2][8][4] = {};
        uint32_t bfA[8][2], bfB[8][2];
        uint4 a0A, a1A, a0B, a1B;

        LOADB(bfA, 0, wc);
        a0A = __ldg(wf + 0);
        a1A = __ldg(wf + 1);

        #pragma unroll 1
        for (int kp = 0; kp < 8; kp++) {
            const int kt0 = 2 * kp;
            // prefetch kt0+1 into B
            LOADB(bfB, kt0 + 1, wc);
            a0B = __ldg(wf + (kt0 + 1) * 2);
            a1B = __ldg(wf + (kt0 + 1) * 2 + 1);
            MMAS(bfA, a0A, a1A);
            // prefetch kt0+2 into A (if any)
            if (kp < 7) {
                LOADB(bfA, kt0 + 2, wc);
                a0A = __ldg(wf + (kt0 + 2) * 2);
                a1A = __ldg(wf + (kt0 + 2) * 2 + 1);
            }
            MMAS(bfB, a0B, a1B);
        }

        // store this w-chunk with ReLU, direct from fragments (streaming)
        #pragma unroll
        for (int mt = 0; mt < 2; mt++) {
            #pragma unroll
            for (int nt = 0; nt < 8; nt++) {
                const int w = wc * 64 + nt * 8 + t * 2;
                float* p0 = outp + ((size_t)(mt * 16) << 16) + w;
                float2 v0 = make_float2(fmaxf(acc[mt][nt][0], 0.f), fmaxf(acc[mt][nt][1], 0.f));
                float2 v1 = make_float2(fmaxf(acc[mt][nt][2], 0.f), fmaxf(acc[mt][nt][3], 0.f));
                __stcs((float2*)p0, v0);
                __stcs((float2*)(p0 + (8 << 16)), v1);   // +8 o-rows
            }
        }
    }
    #undef LOADB
    #undef MMAS
}

extern "C" void kernel_launch(void* const* d_in, const int* in_sizes, int n_in,
                              void* d_out, int out_size) {
    (void)in_sizes; (void)n_in; (void)out_size;
    const float* x   = (const float*)d_in[0];
    const float* y   = (const float*)d_in[1];
    const float* lnw = (const float*)d_in[2];
    const float* lnb = (const float*)d_in[3];
    const float* cw  = (const float*)d_in[4];
    float* out = (float*)d_out;

    cudaFuncSetAttribute(fused_ln_conv_relu, cudaFuncAttributeMaxDynamicSharedMemorySize, SMEM_TOTAL);

    prep_weights<<<128, 256>>>(cw);
    fused_ln_conv_relu<<<1024, 256, SMEM_TOTAL>>>(x, y, lnw, lnb, out);
}